// round 12
// baseline (speedup 1.0000x reference)
#include <cuda_runtime.h>
#include <cuda_fp16.h>
#include <cstdint>
#include <cstddef>

// ---------------- problem constants ----------------
#define BATCH   16
#define NSIZE   512
#define FRAMES  2049                  // T+1 output frames
#define XLEN    (NSIZE * 2048)        // samples per batch = 1048576
#define KF      512                   // folded K (1024 -> 512 via MDCT symmetry)

// ---------------- GEMM tiling ----------------
#define MT      128                   // channel tile
#define NTL     256                   // frame tile
#define KC      64                    // K chunk (64 fp16 = 128B = SW128 atom)
#define NCH     (KF / KC)             // 8 chunks
#define STAGES  4
#define A_BYTES (MT * KC * 2)         // 16 KB
#define B_BYTES (NTL * KC * 2)        // 32 KB
#define STAGE_BYTES (A_BYTES + B_BYTES)     // 48 KB
#define SMEM_TOTAL  (STAGES * STAGE_BYTES)  // 192 KB

// ---------------- scratch (device globals: allocation-free) ----------------
static __device__ __align__(16) __half g_u [(size_t)BATCH * FRAMES * KF];  // 33.6 MB
static __device__ __align__(16) __half g_gh[NSIZE * KF];                    // folded filter (fp16)

// ---------------- PTX helpers ----------------
__device__ __forceinline__ uint32_t smem_u32(const void* p) {
    uint32_t a;
    asm("{ .reg .u64 t; cvta.to.shared.u64 t, %1; cvt.u32.u64 %0, t; }" : "=r"(a) : "l"(p));
    return a;
}

__device__ __forceinline__ void cpa16(uint32_t dst, const void* src) {
    asm volatile("cp.async.cg.shared.global [%0], [%1], 16;"
                 :: "r"(dst), "l"(src) : "memory");
}

#define CP_COMMIT() asm volatile("cp.async.commit_group;" ::: "memory")
#define CP_WAIT2()  asm volatile("cp.async.wait_group 2;" ::: "memory")

#define LDSM4(r0, r1, r2, r3, ad)                                              \
    asm volatile("ldmatrix.sync.aligned.m8n8.x4.shared.b16 {%0,%1,%2,%3}, [%4];" \
                 : "=r"(r0), "=r"(r1), "=r"(r2), "=r"(r3) : "r"(ad))

#define MMA16816(cr, a0, a1, a2, a3, b0, b1)                                   \
    asm volatile("mma.sync.aligned.m16n8k16.row.col.f32.f16.f16.f32 "          \
                 "{%0,%1,%2,%3}, {%4,%5,%6,%7}, {%8,%9}, {%0,%1,%2,%3};"       \
                 : "+f"((cr)[0]), "+f"((cr)[1]), "+f"((cr)[2]), "+f"((cr)[3])  \
                 : "r"(a0), "r"(a1), "r"(a2), "r"(a3), "r"(b0), "r"(b1))

__device__ __forceinline__ uint32_t swz(uint32_t off) {
    return off ^ ((off >> 3) & 0x70);
}

// ---------------- prepass 1: fold filter -> fp16 ----------------
// g[k,n] = f[k, n<256 ? n : n+256]
__global__ void __launch_bounds__(256) mdct_wfold(const float* __restrict__ w) {
    int i = blockIdx.x * 256 + threadIdx.x;      // < 512*512
    int k = i >> 9, n = i & 511;
    int t = n + ((n >> 8) << 8);                  // n<256: n ; n>=256: n+256
    g_gh[i] = __float2half_rn(w[k * 1024 + t]);
}

// ---------------- prepass 2: segment-indexed fold (each x sample read ONCE) ----------------
// Segment s = x[b, s*512 .. s*512+511].
//   frame s+1 first half:  u[s+1, i]     = seg[i] - seg[511-i]   (i < 256)
//   frame s   second half: u[s,   256+i] = seg[i] + seg[511-i]
// Boundary zeros: u[0, 0..255] (s==0), u[2048, 256..511] (s==2047).
__global__ void __launch_bounds__(256) mdct_fold2(const float* __restrict__ x) {
    int seg_in_blk = threadIdx.x >> 6;            // 4 segments per block
    int t = threadIdx.x & 63;                     // 64 threads per segment
    int s = blockIdx.x * 4 + seg_in_blk;          // 0..2047
    int b = blockIdx.y;
    int i4 = t * 4;                               // i = i4..i4+3

    const float* seg = x + (size_t)b * XLEN + (size_t)s * NSIZE;
    float4 a = *(const float4*)(seg + i4);
    float4 r = *(const float4*)(seg + 508 - i4);

    float d0 = a.x - r.w, d1 = a.y - r.z, d2 = a.z - r.y, d3 = a.w - r.x;
    float p0 = a.x + r.w, p1 = a.y + r.z, p2 = a.z + r.y, p3 = a.w + r.x;

    __half2 dh01 = __floats2half2_rn(d0, d1), dh23 = __floats2half2_rn(d2, d3);
    __half2 ph01 = __floats2half2_rn(p0, p1), ph23 = __floats2half2_rn(p2, p3);
    uint2 dv, pv;
    dv.x = *(uint32_t*)&dh01; dv.y = *(uint32_t*)&dh23;
    pv.x = *(uint32_t*)&ph01; pv.y = *(uint32_t*)&ph23;

    __half* ub = g_u + (size_t)b * FRAMES * KF;
    *(uint2*)(ub + (size_t)(s + 1) * KF + i4)       = dv;   // frame s+1, first half
    *(uint2*)(ub + (size_t)s       * KF + 256 + i4) = pv;   // frame s,   second half

    if (s == 0)    *(uint2*)(ub + i4) = make_uint2(0, 0);                         // u[0, first half] = 0
    if (s == 2047) *(uint2*)(ub + (size_t)2048 * KF + 256 + i4) = make_uint2(0, 0); // u[2048, second half] = 0
}

// ---------------- tail: output column f = 2048 (only first 256 K terms nonzero) ----------------
__global__ void __launch_bounds__(256) mdct_tail(float* __restrict__ out) {
    int k = blockIdx.x * 256 + threadIdx.x;       // 0..511 (grid.x = 2)
    int b = blockIdx.y;
    __shared__ float us[256];
    {
        const __half* up = g_u + ((size_t)b * FRAMES + 2048) * KF;
        us[threadIdx.x] = __half2float(up[threadIdx.x]);
    }
    __syncthreads();
    const __half2* grow = (const __half2*)(g_gh + k * KF);
    float sum = 0.f;
#pragma unroll 8
    for (int n2 = 0; n2 < 128; n2++) {
        float2 g2 = __half22float2(grow[n2]);
        sum += g2.x * us[n2 * 2] + g2.y * us[n2 * 2 + 1];
    }
    out[((size_t)b * NSIZE + k) * FRAMES + 2048] = sum;
}

// ---------------- main GEMM: out[b,k,f] = sum_n g[k,n] * u[b,f,n]  (f < 2048) ----------------
__device__ __forceinline__ void load_stage(uint32_t sb, int stage, int kc,
                                           int m0, int f0, int b, int tid) {
    uint32_t base = sb + stage * STAGE_BYTES;
    int c = tid & 7;                    // 16B column
    int r0 = tid >> 3;                  // base row (0..63)
    int kcol = kc * KC + c * 8;
    // A (filter): 128 rows -> 2 per thread
#pragma unroll
    for (int i = 0; i < 2; i++) {
        int row = r0 + i * 64;
        uint32_t sw = swz((row << 7) | (c << 4));
        cpa16(base + sw, g_gh + (m0 + row) * KF + kcol);
    }
    // B (folded frames): 256 rows -> 4 per thread (all frames valid: f0+row <= 2047)
    const __half* ub = g_u + ((size_t)b * FRAMES + f0) * KF + kcol;
#pragma unroll
    for (int i = 0; i < 4; i++) {
        int row = r0 + i * 64;
        uint32_t sw = swz((row << 7) | (c << 4));
        cpa16(base + A_BYTES + sw, ub + (size_t)row * KF);
    }
}

extern "C" __global__ void __launch_bounds__(512, 1) mdct_gemm(float* __restrict__ out) {
    extern __shared__ char smem[];
    const uint32_t sb = smem_u32(smem);
    const int tid = threadIdx.x;
    const int lane = tid & 31;
    const int wid = tid >> 5;           // 0..15
    const int wm = wid & 3;             // warp M index (4): 32 rows each
    const int wn = wid >> 2;            // warp N index (4): 64 cols each

    const int m0 = blockIdx.x * MT;     // channel tile
    const int f0 = blockIdx.y * NTL;    // frame tile (0..1792)
    const int b  = blockIdx.z;

    // ldmatrix lane addressing (row within 16-row tile, 16B column half)
    const int rowSel = (((lane >> 3) & 1) << 3) | (lane & 7);
    const int colSel = (lane >> 4) << 4;

    float C[2][8][4];
#pragma unroll
    for (int mt = 0; mt < 2; mt++)
#pragma unroll
        for (int nt = 0; nt < 8; nt++)
#pragma unroll
            for (int j = 0; j < 4; j++) C[mt][nt][j] = 0.f;

    // prologue: stages 0..2
#pragma unroll
    for (int s = 0; s < STAGES - 1; s++) {
        load_stage(sb, s, s, m0, f0, b, tid);
        CP_COMMIT();
    }

    for (int kc = 0; kc < NCH; kc++) {
        CP_WAIT2();
        __syncthreads();

        if (kc + STAGES - 1 < NCH)
            load_stage(sb, (kc + STAGES - 1) & (STAGES - 1), kc + STAGES - 1, m0, f0, b, tid);
        CP_COMMIT();

        const uint32_t aB = sb + (kc & (STAGES - 1)) * STAGE_BYTES;
        const uint32_t bB = aB + A_BYTES;

#pragma unroll
        for (int s = 0; s < 4; s++) {
            const int kb = s * 32 + colSel;

            // B fragments: 8 n8-tiles (64 cols) x {k0-7, k8-15}
            uint32_t bf[8][2];
#pragma unroll
            for (int nb = 0; nb < 4; nb++) {
                uint32_t off = (uint32_t)((wn * 64 + nb * 16 + rowSel) << 7) | kb;
                uint32_t ad = bB + swz(off);
                uint32_t r0, r1, r2, r3;
                LDSM4(r0, r1, r2, r3, ad);
                bf[nb * 2][0] = r0; bf[nb * 2][1] = r2;
                bf[nb * 2 + 1][0] = r1; bf[nb * 2 + 1][1] = r3;
            }

#pragma unroll
            for (int mt = 0; mt < 2; mt++) {
                uint32_t off = (uint32_t)((wm * 32 + mt * 16 + rowSel) << 7) | kb;
                uint32_t ad = aB + swz(off);
                uint32_t a0, a1, a2, a3;
                LDSM4(a0, a1, a2, a3, ad);
#pragma unroll
                for (int nt = 0; nt < 8; nt++)
                    MMA16816(C[mt][nt], a0, a1, a2, a3, bf[nt][0], bf[nt][1]);
            }
        }
        __syncthreads();
    }

    // ---- epilogue: C frags -> gmem (out[b, k, f], f-major; all f <= 2047 in-range) ----
    const int rbase = m0 + wm * 32 + (lane >> 2);
    const int cbase = f0 + wn * 64 + (lane & 3) * 2;
#pragma unroll
    for (int mt = 0; mt < 2; mt++) {
#pragma unroll
        for (int nt = 0; nt < 8; nt++) {
            int r = rbase + mt * 16;
            int c = cbase + nt * 8;
            float* p0 = out + ((size_t)(b * NSIZE + r)) * FRAMES;
            float* p1 = p0 + 8 * FRAMES;          // row r+8
            p0[c]     = C[mt][nt][0];
            p0[c + 1] = C[mt][nt][1];
            p1[c]     = C[mt][nt][2];
            p1[c + 1] = C[mt][nt][3];
        }
    }
}

// ---------------- launch ----------------
extern "C" void kernel_launch(void* const* d_in, const int* in_sizes, int n_in,
                              void* d_out, int out_size) {
    (void)in_sizes; (void)n_in; (void)out_size;
    const float* x = (const float*)d_in[0];       // [16, 1, 1048576] fp32
    const float* w = (const float*)d_in[1];       // [512, 1, 1024] fp32
    float* out = (float*)d_out;                   // [16, 512, 2049] fp32

    cudaFuncSetAttribute(mdct_gemm, cudaFuncAttributeMaxDynamicSharedMemorySize, SMEM_TOTAL);

    mdct_wfold<<<(NSIZE * KF) / 256, 256>>>(w);
    mdct_fold2<<<dim3(512, BATCH), 256>>>(x);

    dim3 grid(NSIZE / MT, 2048 / NTL, BATCH);     // (4, 8, 16) — frames 0..2047
    mdct_gemm<<<grid, 512, SMEM_TOTAL>>>(out);

    mdct_tail<<<dim3(2, BATCH), 256>>>(out);      // frame 2048 column
}

// round 14
// speedup vs baseline: 1.5305x; 1.5305x over previous
#include <cuda_runtime.h>
#include <cuda_fp16.h>
#include <cstdint>
#include <cstddef>

// ---------------- problem constants ----------------
#define BATCH   16
#define NSIZE   512
#define FRAMES  2049                  // T+1 output frames
#define XLEN    (NSIZE * 2048)        // samples per batch = 1048576
#define KF      512                   // folded K (1024 -> 512 via MDCT symmetry)

// ---------------- GEMM tiling ----------------
#define MT      128                   // channel tile
#define NTL     256                   // frame tile
#define KC      64                    // K chunk (64 fp16 = 128B = SW128 atom)
#define NCH     (KF / KC)             // 8 chunks
#define STAGES  4
#define A_BYTES (MT * KC * 2)         // 16 KB
#define B_BYTES (NTL * KC * 2)        // 32 KB
#define STAGE_BYTES (A_BYTES + B_BYTES)     // 48 KB
#define SMEM_TOTAL  (STAGES * STAGE_BYTES)  // 192 KB

// ---------------- scratch (device globals: allocation-free) ----------------
static __device__ __align__(16) __half g_u [(size_t)BATCH * FRAMES * KF];  // 33.6 MB
static __device__ __align__(16) __half g_gh[NSIZE * KF];                    // folded filter (fp16)

// ---------------- PTX helpers ----------------
__device__ __forceinline__ uint32_t smem_u32(const void* p) {
    uint32_t a;
    asm("{ .reg .u64 t; cvta.to.shared.u64 t, %1; cvt.u32.u64 %0, t; }" : "=r"(a) : "l"(p));
    return a;
}

__device__ __forceinline__ void cpa16(uint32_t dst, const void* src, int src_size) {
    asm volatile("cp.async.cg.shared.global [%0], [%1], 16, %2;"
                 :: "r"(dst), "l"(src), "r"(src_size) : "memory");
}

#define CP_COMMIT() asm volatile("cp.async.commit_group;" ::: "memory")
#define CP_WAIT2()  asm volatile("cp.async.wait_group 2;" ::: "memory")

#define LDSM4(r0, r1, r2, r3, ad)                                              \
    asm volatile("ldmatrix.sync.aligned.m8n8.x4.shared.b16 {%0,%1,%2,%3}, [%4];" \
                 : "=r"(r0), "=r"(r1), "=r"(r2), "=r"(r3) : "r"(ad))

#define MMA16816(cr, a0, a1, a2, a3, b0, b1)                                   \
    asm volatile("mma.sync.aligned.m16n8k16.row.col.f32.f16.f16.f32 "          \
                 "{%0,%1,%2,%3}, {%4,%5,%6,%7}, {%8,%9}, {%0,%1,%2,%3};"       \
                 : "+f"((cr)[0]), "+f"((cr)[1]), "+f"((cr)[2]), "+f"((cr)[3])  \
                 : "r"(a0), "r"(a1), "r"(a2), "r"(a3), "r"(b0), "r"(b1))

__device__ __forceinline__ uint32_t swz(uint32_t off) {
    return off ^ ((off >> 3) & 0x70);
}

// ---------------- prepass 1: fold filter -> fp16 ----------------
// g[k,n] = f[k, n<256 ? n : n+256]
__global__ void __launch_bounds__(256) mdct_wfold(const float* __restrict__ w) {
    int i = blockIdx.x * 256 + threadIdx.x;      // < 512*512
    int k = i >> 9, n = i & 511;
    int t = n + ((n >> 8) << 8);                  // n<256: n ; n>=256: n+256
    g_gh[i] = __float2half_rn(w[k * 1024 + t]);
}

// ---------------- prepass 2: segment-indexed fold (each x sample read ONCE) ----------------
// Segment s = x[b, s*512 .. s*512+511].
//   frame s+1 first half:  u[s+1, i]     = seg[i] - seg[511-i]   (i < 256)
//   frame s   second half: u[s,   256+i] = seg[i] + seg[511-i]
// Boundary zeros: u[0, 0..255] (s==0), u[2048, 256..511] (s==2047).
__global__ void __launch_bounds__(256) mdct_fold2(const float* __restrict__ x) {
    int seg_in_blk = threadIdx.x >> 6;            // 4 segments per block
    int t = threadIdx.x & 63;                     // 64 threads per segment
    int s = blockIdx.x * 4 + seg_in_blk;          // 0..2047
    int b = blockIdx.y;
    int i4 = t * 4;                               // i = i4..i4+3

    const float* seg = x + (size_t)b * XLEN + (size_t)s * NSIZE;
    float4 a = *(const float4*)(seg + i4);
    float4 r = *(const float4*)(seg + 508 - i4);

    float d0 = a.x - r.w, d1 = a.y - r.z, d2 = a.z - r.y, d3 = a.w - r.x;
    float p0 = a.x + r.w, p1 = a.y + r.z, p2 = a.z + r.y, p3 = a.w + r.x;

    __half2 dh01 = __floats2half2_rn(d0, d1), dh23 = __floats2half2_rn(d2, d3);
    __half2 ph01 = __floats2half2_rn(p0, p1), ph23 = __floats2half2_rn(p2, p3);
    uint2 dv, pv;
    dv.x = *(uint32_t*)&dh01; dv.y = *(uint32_t*)&dh23;
    pv.x = *(uint32_t*)&ph01; pv.y = *(uint32_t*)&ph23;

    __half* ub = g_u + (size_t)b * FRAMES * KF;
    *(uint2*)(ub + (size_t)(s + 1) * KF + i4)       = dv;   // frame s+1, first half
    *(uint2*)(ub + (size_t)s       * KF + 256 + i4) = pv;   // frame s,   second half

    if (s == 0)    *(uint2*)(ub + i4) = make_uint2(0, 0);                           // u[0, first half]
    if (s == 2047) *(uint2*)(ub + (size_t)2048 * KF + 256 + i4) = make_uint2(0, 0); // u[2048, second half]
}

// ---------------- main GEMM: out[b,k,f] = sum_n g[k,n] * u[b,f,n] ----------------
__device__ __forceinline__ void load_stage(uint32_t sb, int stage, int kc,
                                           int m0, int f0, int b, int tid) {
    uint32_t base = sb + stage * STAGE_BYTES;
    int c = tid & 7;                    // 16B column
    int r0 = tid >> 3;                  // base row (0..31)
    int kcol = kc * KC + c * 8;
    // A (filter): 128 rows x 8 segs = 1024 -> 4 per thread
#pragma unroll
    for (int i = 0; i < 4; i++) {
        int row = r0 + i * 32;
        uint32_t sw = swz((row << 7) | (c << 4));
        cpa16(base + sw, g_gh + (m0 + row) * KF + kcol, 16);
    }
    // B (folded frames): 256 rows x 8 segs = 2048 -> 8 per thread
#pragma unroll
    for (int i = 0; i < 8; i++) {
        int row = r0 + i * 32;
        uint32_t sw = swz((row << 7) | (c << 4));
        int f = f0 + row;
        int valid = (f <= 2048) ? 16 : 0;
        size_t fr = (f <= 2048) ? (size_t)(b * FRAMES + f) : 0;
        cpa16(base + A_BYTES + sw, g_u + fr * KF + kcol, valid);
    }
}

extern "C" __global__ void __launch_bounds__(256, 1) mdct_gemm(float* __restrict__ out) {
    extern __shared__ char smem[];
    const uint32_t sb = smem_u32(smem);
    const int tid = threadIdx.x;
    const int lane = tid & 31;
    const int wid = tid >> 5;
    const int wm = wid & 1;             // warp M index (2): 64 rows each
    const int wn = wid >> 1;            // warp N index (4): 64 cols each

    const int m0 = blockIdx.x * MT;     // channel tile
    const int f0 = blockIdx.y * NTL;    // frame tile
    const int b  = blockIdx.z;

    // ldmatrix lane addressing (row within 16-row tile, 16B column half)
    const int rowSel = (((lane >> 3) & 1) << 3) | (lane & 7);
    const int colSel = (lane >> 4) << 4;

    float C[4][8][4];
#pragma unroll
    for (int mt = 0; mt < 4; mt++)
#pragma unroll
        for (int nt = 0; nt < 8; nt++)
#pragma unroll
            for (int j = 0; j < 4; j++) C[mt][nt][j] = 0.f;

    // prologue: stages 0..2
#pragma unroll
    for (int s = 0; s < STAGES - 1; s++) {
        load_stage(sb, s, s, m0, f0, b, tid);
        CP_COMMIT();
    }

    for (int kc = 0; kc < NCH; kc++) {
        // Single barrier per chunk: orders (a) arrival of stage kc for all warps,
        // and (b) previous iteration's reads of the stage that load_stage below
        // will overwrite (stage (kc+3)&3 == (kc-1)&3, last read at iter kc-1).
        CP_WAIT2();
        __syncthreads();

        if (kc + STAGES - 1 < NCH)
            load_stage(sb, (kc + STAGES - 1) & (STAGES - 1), kc + STAGES - 1, m0, f0, b, tid);
        CP_COMMIT();

        const uint32_t aB = sb + (kc & (STAGES - 1)) * STAGE_BYTES;
        const uint32_t bB = aB + A_BYTES;

#pragma unroll
        for (int s = 0; s < 4; s++) {
            const int kb = s * 32 + colSel;

            // B fragments: 8 n8-tiles (64 cols) x {k0-7, k8-15}
            uint32_t bf[8][2];
#pragma unroll
            for (int nb = 0; nb < 4; nb++) {
                uint32_t off = (uint32_t)((wn * 64 + nb * 16 + rowSel) << 7) | kb;
                uint32_t ad = bB + swz(off);
                uint32_t r0, r1, r2, r3;
                LDSM4(r0, r1, r2, r3, ad);
                bf[nb * 2][0] = r0; bf[nb * 2][1] = r2;
                bf[nb * 2 + 1][0] = r1; bf[nb * 2 + 1][1] = r3;
            }

#pragma unroll
            for (int mt = 0; mt < 4; mt++) {
                uint32_t off = (uint32_t)((wm * 64 + mt * 16 + rowSel) << 7) | kb;
                uint32_t ad = aB + swz(off);
                uint32_t a0, a1, a2, a3;
                LDSM4(a0, a1, a2, a3, ad);
#pragma unroll
                for (int nt = 0; nt < 8; nt++)
                    MMA16816(C[mt][nt], a0, a1, a2, a3, bf[nt][0], bf[nt][1]);
            }
        }
    }

    // ---- epilogue: C frags -> gmem (out[b, k, f], f-major, FRAMES=2049) ----
    const int rbase = m0 + wm * 64 + (lane >> 2);
    const int cbase = f0 + wn * 64 + (lane & 3) * 2;
#pragma unroll
    for (int mt = 0; mt < 4; mt++) {
#pragma unroll
        for (int nt = 0; nt < 8; nt++) {
            int r = rbase + mt * 16;
            int c = cbase + nt * 8;
            float* p0 = out + ((size_t)(b * NSIZE + r)) * FRAMES;
            float* p1 = p0 + 8 * FRAMES;          // row r+8
            if (c < FRAMES) {
                p0[c] = C[mt][nt][0];
                p1[c] = C[mt][nt][2];
                if (c + 1 < FRAMES) {
                    p0[c + 1] = C[mt][nt][1];
                    p1[c + 1] = C[mt][nt][3];
                }
            }
        }
    }
}

// ---------------- launch ----------------
extern "C" void kernel_launch(void* const* d_in, const int* in_sizes, int n_in,
                              void* d_out, int out_size) {
    (void)in_sizes; (void)n_in; (void)out_size;
    const float* x = (const float*)d_in[0];       // [16, 1, 1048576] fp32
    const float* w = (const float*)d_in[1];       // [512, 1, 1024] fp32
    float* out = (float*)d_out;                   // [16, 512, 2049] fp32

    cudaFuncSetAttribute(mdct_gemm, cudaFuncAttributeMaxDynamicSharedMemorySize, SMEM_TOTAL);

    mdct_wfold<<<(NSIZE * KF) / 256, 256>>>(w);
    mdct_fold2<<<dim3(512, BATCH), 256>>>(x);

    dim3 grid(NSIZE / MT, (2048 + NTL) / NTL, BATCH);   // (4, 9, 16) — frames 0..2048, masked
    mdct_gemm<<<grid, 256, SMEM_TOTAL>>>(out);
}